// round 16
// baseline (speedup 1.0000x reference)
#include <cuda_runtime.h>
#include <cuda_bf16.h>
#include <cstdint>
#include <math.h>

#define BATCH 16
#define LSEQ  8192
#define DDIM  256

#define KSPLIT 3
#define KC     32
#define NCHUNKS (LSEQ / KC)        // 256

// ---------------------------------------------------------------------------
// Static device scratch
// ---------------------------------------------------------------------------
__device__ float g_norm[BATCH * LSEQ];
__device__ float g_psum[BATCH * 64];
__device__ float g_sw[BATCH * LSEQ];
__device__ float g_part[BATCH * 3 * KSPLIT * 128 * 128];   // 9.4 MB
__device__ int   g_cnt[BATCH * 3];                         // finisher counters (0-init)

// ---------------------------------------------------------------------------
// Helpers
// ---------------------------------------------------------------------------
__device__ __forceinline__ uint32_t smem_u32(const void* p) {
    uint32_t a;
    asm("{ .reg .u64 t; cvta.to.shared.u64 t, %1; cvt.u32.u64 %0, t; }"
        : "=r"(a) : "l"(p));
    return a;
}

__device__ __forceinline__ void ldsm4t(uint32_t* r, uint32_t addr) {
    asm volatile("ldmatrix.sync.aligned.m8n8.x4.trans.shared.b16 {%0,%1,%2,%3}, [%4];"
                 : "=r"(r[0]), "=r"(r[1]), "=r"(r[2]), "=r"(r[3]) : "r"(addr));
}

__device__ __forceinline__ void mma16816(float* c, const uint32_t* a,
                                         uint32_t b0, uint32_t b1) {
    asm volatile(
        "mma.sync.aligned.m16n8k16.row.col.f32.bf16.bf16.f32 "
        "{%0,%1,%2,%3}, {%4,%5,%6,%7}, {%8,%9}, {%0,%1,%2,%3};"
        : "+f"(c[0]), "+f"(c[1]), "+f"(c[2]), "+f"(c[3])
        : "r"(a[0]), "r"(a[1]), "r"(a[2]), "r"(a[3]), "r"(b0), "r"(b1));
}

#define STS128(addr, r0, r1, r2, r3) \
    asm volatile("st.shared.v4.b32 [%0], {%1,%2,%3,%4};" \
                 :: "r"(addr), "r"(r0), "r"(r1), "r"(r2), "r"(r3))

// bf16 hi/lo split of a scaled float4 -> packed pairs
__device__ __forceinline__ void split4(float4 v, float wv,
                                       uint32_t& h0, uint32_t& h1,
                                       uint32_t& lo0, uint32_t& lo1) {
    v.x *= wv; v.y *= wv; v.z *= wv; v.w *= wv;
    asm("cvt.rn.bf16x2.f32 %0, %1, %2;" : "=r"(h0) : "f"(v.y), "f"(v.x));
    asm("cvt.rn.bf16x2.f32 %0, %1, %2;" : "=r"(h1) : "f"(v.w), "f"(v.z));
    float r0 = v.x - __uint_as_float(h0 << 16);
    float r1 = v.y - __uint_as_float(h0 & 0xFFFF0000u);
    float r2 = v.z - __uint_as_float(h1 << 16);
    float r3 = v.w - __uint_as_float(h1 & 0xFFFF0000u);
    asm("cvt.rn.bf16x2.f32 %0, %1, %2;" : "=r"(lo0) : "f"(r1), "f"(r0));
    asm("cvt.rn.bf16x2.f32 %0, %1, %2;" : "=r"(lo1) : "f"(r3), "f"(r2));
}

// ---------------------------------------------------------------------------
// Stage A1: per-row L2 norms + per-block partial sums of exp(norm).
// 2 rows per warp-iteration -> 4 LDGs in flight, interleaved shfl chains.
// ---------------------------------------------------------------------------
__global__ __launch_bounds__(256) void norms_kernel(const float* __restrict__ x)
{
    const int b    = blockIdx.y;
    const int r0   = blockIdx.x * 128;
    const int warp = threadIdx.x >> 5;
    const int lane = threadIdx.x & 31;
    const float* xb = x + (size_t)b * LSEQ * DDIM;

    __shared__ float sp[8];
    float esum = 0.f;

#pragma unroll 2
    for (int i = 0; i < 16; i += 2) {
        const int la = r0 + warp * 16 + i;
        const int lb = la + 1;
        const float4* rowa = (const float4*)(xb + (size_t)la * DDIM);
        const float4* rowb = (const float4*)(xb + (size_t)lb * DDIM);
        float4 a1 = rowa[lane];
        float4 a2 = rowa[lane + 32];
        float4 b1 = rowb[lane];
        float4 b2 = rowb[lane + 32];
        float sa = a1.x * a1.x + a1.y * a1.y + a1.z * a1.z + a1.w * a1.w
                 + a2.x * a2.x + a2.y * a2.y + a2.z * a2.z + a2.w * a2.w;
        float sb2 = b1.x * b1.x + b1.y * b1.y + b1.z * b1.z + b1.w * b1.w
                 + b2.x * b2.x + b2.y * b2.y + b2.z * b2.z + b2.w * b2.w;
#pragma unroll
        for (int o = 16; o; o >>= 1) {
            sa  += __shfl_xor_sync(0xffffffffu, sa, o);
            sb2 += __shfl_xor_sync(0xffffffffu, sb2, o);
        }
        if (lane == 0) {
            float na = sqrtf(sa), nb = sqrtf(sb2);
            g_norm[b * LSEQ + la] = na;
            g_norm[b * LSEQ + lb] = nb;
            esum += __expf(na) + __expf(nb);
        }
    }
    if (lane == 0) sp[warp] = esum;
    __syncthreads();
    if (warp == 0) {
        float t = (lane < 8) ? sp[lane] : 0.f;
#pragma unroll
        for (int o = 4; o; o >>= 1) t += __shfl_xor_sync(0xffffffffu, t, o);
        if (lane == 0) g_psum[b * 64 + blockIdx.x] = t;
    }
}

// ---------------------------------------------------------------------------
// Stage A2: sw = exp(n/2) / sqrt(S).  grid (32, 16).
// ---------------------------------------------------------------------------
__global__ __launch_bounds__(256) void scale_kernel()
{
    const int b   = blockIdx.y;
    const int tid = threadIdx.x;
    __shared__ float sred[2];

    if (tid < 64) {
        float t = g_psum[b * 64 + tid];
#pragma unroll
        for (int o = 16; o; o >>= 1) t += __shfl_xor_sync(0xffffffffu, t, o);
        if ((tid & 31) == 0) sred[tid >> 5] = t;
    }
    __syncthreads();
    const float rs = rsqrtf(sred[0] + sred[1]);

    const int l = blockIdx.x * 256 + tid;
    const float n = g_norm[b * LSEQ + l];
    g_sw[b * LSEQ + l] = __expf(0.5f * n) * rs;
}

// ---------------------------------------------------------------------------
// Stage B: R12's proven inner loop (convert overlapped with MMA, 4-slot ring,
// barrier every 2 chunks) + fused split-K reduce in the last CTA's tail.
// 512 threads, occ 1, warp tile 32x32; grid (9,16) = one wave.
// ---------------------------------------------------------------------------
#define SP   136
#define SPB  272
#define ABYTES (KC * SPB)          // 8704
#define SLOT   (4 * ABYTES)        // 34816
#define SM_TOT (4 * SLOT)          // 139264

__global__ __launch_bounds__(512, 1) void tensor_gemm(const float* __restrict__ x,
                                                      float* __restrict__ out)
{
    extern __shared__ __align__(16) char dsm[];
    const uint32_t sb = smem_u32(dsm);

    const int tid  = threadIdx.x;
    const int wid  = tid >> 5;        // 0..15
    const int lane = tid & 31;

    const int tile = blockIdx.x / KSPLIT;   // 0:(0,0) 1:(0,1) 2:(1,1)
    const int s    = blockIdx.x % KSPLIT;
    const int b    = blockIdx.y;
    const int ti   = (tile == 2) ? 1 : 0;
    const int tj   = (tile >= 1) ? 1 : 0;
    const bool diag = (ti == tj);

    const float* xb  = x + (size_t)b * LSEQ * DDIM;
    const float* swb = g_sw + b * LSEQ;
    const int c0A = ti * 128;
    const int c0B = tj * 128;

    // chunk partition over 256: 86,85,85
    const int c_start = (s == 0) ? 0 : 86 + (s - 1) * 85;
    const int c_end   = c_start + ((s == 0) ? 86 : 85);

    const int wy = wid & 3;          // 32-row group
    const int wx = wid >> 2;         // 32-col group

    const uint32_t offA = ((lane & 7) + ((lane >> 4) & 1) * 8) * SPB
                        + ((lane >> 3) & 1) * 16;
    const uint32_t offB = ((lane & 7) + ((lane >> 3) & 1) * 8) * SPB
                        + ((lane >> 4) & 1) * 16;

    // convert mapping: lane -> (row, 8-col block)
    const int crow = wid * 2 + (lane >> 4);            // 0..31
    const int cq   = lane & 15;                        // cols [8cq, 8cq+8)
    const uint32_t cvoff = (uint32_t)crow * SPB + (uint32_t)cq * 16;

    float acc[2][4][4];
#pragma unroll
    for (int m = 0; m < 2; m++)
#pragma unroll
        for (int n = 0; n < 4; n++)
#pragma unroll
            for (int q = 0; q < 4; q++) acc[m][n][q] = 0.f;

    float4 pa0, pa1, pb0, pb1;
    float  pw;

#define SLOTADDR(cc) (sb + (uint32_t)((cc) & 3) * SLOT)

#define LOADREGS(cc) do { \
        const int l_ = (cc) * KC + crow; \
        pw = swb[l_]; \
        const float4* rp_ = (const float4*)(xb + (size_t)l_ * DDIM + c0A); \
        pa0 = rp_[cq * 2]; pa1 = rp_[cq * 2 + 1]; \
        if (!diag) { \
            const float4* rq_ = (const float4*)(xb + (size_t)l_ * DDIM + c0B); \
            pb0 = rq_[cq * 2]; pb1 = rq_[cq * 2 + 1]; \
        } \
    } while (0)

#define CONVREGS(base_) do { \
        const uint32_t yaH_ = (base_); \
        const uint32_t yaL_ = (base_) + ABYTES; \
        uint32_t h0, h1, h2, h3, q0, q1, q2, q3; \
        split4(pa0, pw, h0, h1, q0, q1); \
        split4(pa1, pw, h2, h3, q2, q3); \
        STS128(yaH_ + cvoff, h0, h1, h2, h3); \
        STS128(yaL_ + cvoff, q0, q1, q2, q3); \
        if (!diag) { \
            const uint32_t ybH_ = (base_) + 2 * ABYTES; \
            const uint32_t ybL_ = (base_) + 3 * ABYTES; \
            split4(pb0, pw, h0, h1, q0, q1); \
            split4(pb1, pw, h2, h3, q2, q3); \
            STS128(ybH_ + cvoff, h0, h1, h2, h3); \
            STS128(ybL_ + cvoff, q0, q1, q2, q3); \
        } \
    } while (0)

#define MMASTEP(kk_, yaH_, yaL_, ybH_, ybL_) do { \
        const uint32_t krow_ = (uint32_t)((kk_) * 16) * SPB; \
        const uint32_t aBH_ = (yaH_) + offA + (uint32_t)(wy * 64); \
        const uint32_t aBL_ = (yaL_) + offA + (uint32_t)(wy * 64); \
        const uint32_t bBH_ = (ybH_) + offB + (uint32_t)(wx * 64); \
        const uint32_t bBL_ = (ybL_) + offB + (uint32_t)(wx * 64); \
        uint32_t ah[2][4], bh[2][4], xx[2][4]; \
        _Pragma("unroll") \
        for (int m = 0; m < 2; m++) ldsm4t(ah[m], aBH_ + krow_ + m * 32); \
        _Pragma("unroll") \
        for (int j = 0; j < 2; j++) ldsm4t(bh[j], bBH_ + krow_ + j * 32); \
        _Pragma("unroll") \
        for (int m = 0; m < 2; m++) \
            _Pragma("unroll") \
            for (int j = 0; j < 2; j++) { \
                mma16816(acc[m][j * 2 + 0], ah[m], bh[j][0], bh[j][1]); \
                mma16816(acc[m][j * 2 + 1], ah[m], bh[j][2], bh[j][3]); \
            } \
        _Pragma("unroll") \
        for (int j = 0; j < 2; j++) ldsm4t(xx[j], bBL_ + krow_ + j * 32); \
        _Pragma("unroll") \
        for (int m = 0; m < 2; m++) \
            _Pragma("unroll") \
            for (int j = 0; j < 2; j++) { \
                mma16816(acc[m][j * 2 + 0], ah[m], xx[j][0], xx[j][1]); \
                mma16816(acc[m][j * 2 + 1], ah[m], xx[j][2], xx[j][3]); \
            } \
        _Pragma("unroll") \
        for (int m = 0; m < 2; m++) ldsm4t(xx[m], aBL_ + krow_ + m * 32); \
        _Pragma("unroll") \
        for (int m = 0; m < 2; m++) \
            _Pragma("unroll") \
            for (int j = 0; j < 2; j++) { \
                mma16816(acc[m][j * 2 + 0], xx[m], bh[j][0], bh[j][1]); \
                mma16816(acc[m][j * 2 + 1], xx[m], bh[j][2], bh[j][3]); \
            } \
    } while (0)

    // -------- prologue: convert chunks c_start, c_start+1; LDG c_start+2 ----
    LOADREGS(c_start);
    CONVREGS(SLOTADDR(c_start));
    if (c_start + 1 < c_end) {
        LOADREGS(c_start + 1);
        CONVREGS(SLOTADDR(c_start + 1));
    }
    if (c_start + 2 < c_end) LOADREGS(c_start + 2);
    __syncthreads();

    for (int c = c_start; c < c_end; c++) {
        const uint32_t bM = SLOTADDR(c);
        const uint32_t yaH = bM;
        const uint32_t yaL = bM + ABYTES;
        const uint32_t ybH = diag ? yaH : bM + 2 * ABYTES;
        const uint32_t ybL = diag ? yaL : bM + 3 * ABYTES;

        MMASTEP(0, yaH, yaL, ybH, ybL);

        if (c + 2 < c_end) CONVREGS(SLOTADDR(c + 2));
        if (c + 3 < c_end) LOADREGS(c + 3);

        MMASTEP(1, yaH, yaL, ybH, ybL);

        if (((c - c_start) & 1) == 1) __syncthreads();
    }

    // ---- epilogue: write split-K partial tile ----
    float* dst = g_part + (((size_t)b * 3 + tile) * KSPLIT + s) * (128 * 128);
#pragma unroll
    for (int m = 0; m < 2; m++)
#pragma unroll
        for (int j = 0; j < 2; j++)
#pragma unroll
            for (int n = 0; n < 2; n++) {
                const int d = wy * 32 + m * 16 + (lane >> 2);
                const int e = wx * 32 + j * 16 + n * 8 + (lane & 3) * 2;
                float* cc = acc[m][j * 2 + n];
                *(float2*)(dst + d * 128 + e)       = make_float2(cc[0], cc[1]);
                *(float2*)(dst + (d + 8) * 128 + e) = make_float2(cc[2], cc[3]);
            }

    // ---- fused split-K reduce: last CTA per (b, tile) sums partials ----
    __threadfence();
    __shared__ int is_last;
    if (tid == 0) {
        int old = atomicAdd(&g_cnt[b * 3 + tile], 1);
        is_last = (old == KSPLIT - 1) ? 1 : 0;
    }
    __syncthreads();
    if (is_last) {
        __threadfence();   // acquire side
        const float* p = g_part + (((size_t)b * 3 + tile) * KSPLIT) * 16384;
        float* ob = out + (size_t)b * DDIM * DDIM;
        for (int i = tid * 4; i < 16384; i += 512 * 4) {
            float4 v0 = *(const float4*)(p + i);
            float4 v1 = *(const float4*)(p + 16384 + i);
            float4 v2 = *(const float4*)(p + 32768 + i);
            float4 v = make_float4(v0.x + v1.x + v2.x, v0.y + v1.y + v2.y,
                                   v0.z + v1.z + v2.z, v0.w + v1.w + v2.w);
            const int dl = i >> 7, el = i & 127;
            if (tile == 0) {
                *(float4*)(ob + (size_t)dl * DDIM + el) = v;
            } else if (tile == 2) {
                *(float4*)(ob + (size_t)(128 + dl) * DDIM + 128 + el) = v;
            } else {
                *(float4*)(ob + (size_t)dl * DDIM + 128 + el) = v;
                ob[(size_t)(128 + el + 0) * DDIM + dl] = v.x;
                ob[(size_t)(128 + el + 1) * DDIM + dl] = v.y;
                ob[(size_t)(128 + el + 2) * DDIM + dl] = v.z;
                ob[(size_t)(128 + el + 3) * DDIM + dl] = v.w;
            }
        }
        if (tid == 0) atomicExch(&g_cnt[b * 3 + tile], 0);   // reset for graph replay
    }

#undef LOADREGS
#undef CONVREGS
#undef MMASTEP
#undef SLOTADDR
}

// ---------------------------------------------------------------------------
extern "C" void kernel_launch(void* const* d_in, const int* in_sizes, int n_in,
                              void* d_out, int out_size)
{
    const float* x = (const float*)d_in[0];
    float* out = (float*)d_out;

    cudaFuncSetAttribute(tensor_gemm, cudaFuncAttributeMaxDynamicSharedMemorySize, SM_TOT);

    norms_kernel<<<dim3(64, BATCH), 256>>>(x);
    scale_kernel<<<dim3(32, BATCH), 256>>>();
    tensor_gemm<<<dim3(3 * KSPLIT, BATCH), 512, SM_TOT>>>(x, out);
}

// round 17
// speedup vs baseline: 1.0734x; 1.0734x over previous
#include <cuda_runtime.h>
#include <cuda_bf16.h>
#include <cstdint>
#include <math.h>

#define BATCH 16
#define LSEQ  8192
#define DDIM  256

#define KSPLIT 3
#define KC     32
#define NCHUNKS (LSEQ / KC)        // 256

// ---------------------------------------------------------------------------
// Static device scratch
// ---------------------------------------------------------------------------
__device__ float g_norm[BATCH * LSEQ];
__device__ float g_psum[BATCH * 64];
__device__ float g_rs[BATCH];                              // rsqrt(sum exp)
__device__ float g_part[BATCH * 3 * KSPLIT * 128 * 128];   // 9.4 MB

// ---------------------------------------------------------------------------
// Helpers
// ---------------------------------------------------------------------------
__device__ __forceinline__ uint32_t smem_u32(const void* p) {
    uint32_t a;
    asm("{ .reg .u64 t; cvta.to.shared.u64 t, %1; cvt.u32.u64 %0, t; }"
        : "=r"(a) : "l"(p));
    return a;
}

__device__ __forceinline__ void ldsm4t(uint32_t* r, uint32_t addr) {
    asm volatile("ldmatrix.sync.aligned.m8n8.x4.trans.shared.b16 {%0,%1,%2,%3}, [%4];"
                 : "=r"(r[0]), "=r"(r[1]), "=r"(r[2]), "=r"(r[3]) : "r"(addr));
}

__device__ __forceinline__ void mma16816(float* c, const uint32_t* a,
                                         uint32_t b0, uint32_t b1) {
    asm volatile(
        "mma.sync.aligned.m16n8k16.row.col.f32.bf16.bf16.f32 "
        "{%0,%1,%2,%3}, {%4,%5,%6,%7}, {%8,%9}, {%0,%1,%2,%3};"
        : "+f"(c[0]), "+f"(c[1]), "+f"(c[2]), "+f"(c[3])
        : "r"(a[0]), "r"(a[1]), "r"(a[2]), "r"(a[3]), "r"(b0), "r"(b1));
}

#define STS128(addr, r0, r1, r2, r3) \
    asm volatile("st.shared.v4.b32 [%0], {%1,%2,%3,%4};" \
                 :: "r"(addr), "r"(r0), "r"(r1), "r"(r2), "r"(r3))

// bf16 hi/lo split of a scaled float4 -> packed pairs
__device__ __forceinline__ void split4(float4 v, float wv,
                                       uint32_t& h0, uint32_t& h1,
                                       uint32_t& lo0, uint32_t& lo1) {
    v.x *= wv; v.y *= wv; v.z *= wv; v.w *= wv;
    asm("cvt.rn.bf16x2.f32 %0, %1, %2;" : "=r"(h0) : "f"(v.y), "f"(v.x));
    asm("cvt.rn.bf16x2.f32 %0, %1, %2;" : "=r"(h1) : "f"(v.w), "f"(v.z));
    float r0 = v.x - __uint_as_float(h0 << 16);
    float r1 = v.y - __uint_as_float(h0 & 0xFFFF0000u);
    float r2 = v.z - __uint_as_float(h1 << 16);
    float r3 = v.w - __uint_as_float(h1 & 0xFFFF0000u);
    asm("cvt.rn.bf16x2.f32 %0, %1, %2;" : "=r"(lo0) : "f"(r1), "f"(r0));
    asm("cvt.rn.bf16x2.f32 %0, %1, %2;" : "=r"(lo1) : "f"(r3), "f"(r2));
}

// ---------------------------------------------------------------------------
// Stage A1: per-row L2 norms + per-block partial sums of exp(norm).
// 4 rows per warp-iteration -> 8 LDG.128 in flight, interleaved shfl chains.
// ---------------------------------------------------------------------------
__global__ __launch_bounds__(256) void norms_kernel(const float* __restrict__ x)
{
    const int b    = blockIdx.y;
    const int r0   = blockIdx.x * 128;
    const int warp = threadIdx.x >> 5;
    const int lane = threadIdx.x & 31;
    const float* xb = x + (size_t)b * LSEQ * DDIM;

    __shared__ float sp[8];
    float esum = 0.f;

    for (int i = 0; i < 16; i += 4) {
        const int la = r0 + warp * 16 + i;
        float s[4];
#pragma unroll
        for (int r = 0; r < 4; r++) {
            const float4* row = (const float4*)(xb + (size_t)(la + r) * DDIM);
            float4 v1 = row[lane];
            float4 v2 = row[lane + 32];
            s[r] = v1.x * v1.x + v1.y * v1.y + v1.z * v1.z + v1.w * v1.w
                 + v2.x * v2.x + v2.y * v2.y + v2.z * v2.z + v2.w * v2.w;
        }
#pragma unroll
        for (int o = 16; o; o >>= 1) {
#pragma unroll
            for (int r = 0; r < 4; r++)
                s[r] += __shfl_xor_sync(0xffffffffu, s[r], o);
        }
        if (lane == 0) {
#pragma unroll
            for (int r = 0; r < 4; r++) {
                float n = sqrtf(s[r]);
                g_norm[b * LSEQ + la + r] = n;
                esum += __expf(n);
            }
        }
    }
    if (lane == 0) sp[warp] = esum;
    __syncthreads();
    if (warp == 0) {
        float t = (lane < 8) ? sp[lane] : 0.f;
#pragma unroll
        for (int o = 4; o; o >>= 1) t += __shfl_xor_sync(0xffffffffu, t, o);
        if (lane == 0) g_psum[b * 64 + blockIdx.x] = t;
    }
}

// ---------------------------------------------------------------------------
// Stage A2: g_rs[b] = rsqrt(sum of 64 partials).  grid (16), 32 threads.
// ---------------------------------------------------------------------------
__global__ __launch_bounds__(32) void sum_kernel()
{
    const int b   = blockIdx.x;
    const int tid = threadIdx.x;
    float t = g_psum[b * 64 + tid] + g_psum[b * 64 + tid + 32];
#pragma unroll
    for (int o = 16; o; o >>= 1) t += __shfl_xor_sync(0xffffffffu, t, o);
    if (tid == 0) g_rs[b] = rsqrtf(t);
}

// ---------------------------------------------------------------------------
// Stage B: R12's proven inner loop (convert overlapped with MMA, 4-slot ring,
// barrier every 2 chunks). sqrt(softmax) computed INLINE from g_norm:
// pw = exp(n/2) * g_rs[b]  (one MUFU op per chunk per thread).
// 512 threads, occ 1, warp tile 32x32; grid (9,16) = one wave.
// ---------------------------------------------------------------------------
#define SP   136
#define SPB  272
#define ABYTES (KC * SPB)          // 8704
#define SLOT   (4 * ABYTES)        // 34816
#define SM_TOT (4 * SLOT)          // 139264

__global__ __launch_bounds__(512, 1) void tensor_gemm(const float* __restrict__ x)
{
    extern __shared__ __align__(16) char dsm[];
    const uint32_t sb = smem_u32(dsm);

    const int tid  = threadIdx.x;
    const int wid  = tid >> 5;        // 0..15
    const int lane = tid & 31;

    const int tile = blockIdx.x / KSPLIT;   // 0:(0,0) 1:(0,1) 2:(1,1)
    const int s    = blockIdx.x % KSPLIT;
    const int b    = blockIdx.y;
    const int ti   = (tile == 2) ? 1 : 0;
    const int tj   = (tile >= 1) ? 1 : 0;
    const bool diag = (ti == tj);

    const float* xb = x + (size_t)b * LSEQ * DDIM;
    const float* nb = g_norm + b * LSEQ;
    const float rsb = g_rs[b];
    const int c0A = ti * 128;
    const int c0B = tj * 128;

    // chunk partition over 256: 86,85,85
    const int c_start = (s == 0) ? 0 : 86 + (s - 1) * 85;
    const int c_end   = c_start + ((s == 0) ? 86 : 85);

    const int wy = wid & 3;          // 32-row group
    const int wx = wid >> 2;         // 32-col group

    const uint32_t offA = ((lane & 7) + ((lane >> 4) & 1) * 8) * SPB
                        + ((lane >> 3) & 1) * 16;
    const uint32_t offB = ((lane & 7) + ((lane >> 3) & 1) * 8) * SPB
                        + ((lane >> 4) & 1) * 16;

    // convert mapping: lane -> (row, 8-col block)
    const int crow = wid * 2 + (lane >> 4);            // 0..31
    const int cq   = lane & 15;                        // cols [8cq, 8cq+8)
    const uint32_t cvoff = (uint32_t)crow * SPB + (uint32_t)cq * 16;

    float acc[2][4][4];
#pragma unroll
    for (int m = 0; m < 2; m++)
#pragma unroll
        for (int n = 0; n < 4; n++)
#pragma unroll
            for (int q = 0; q < 4; q++) acc[m][n][q] = 0.f;

    float4 pa0, pa1, pb0, pb1;
    float  pw;

#define SLOTADDR(cc) (sb + (uint32_t)((cc) & 3) * SLOT)

#define LOADREGS(cc) do { \
        const int l_ = (cc) * KC + crow; \
        pw = __expf(0.5f * nb[l_]) * rsb; \
        const float4* rp_ = (const float4*)(xb + (size_t)l_ * DDIM + c0A); \
        pa0 = rp_[cq * 2]; pa1 = rp_[cq * 2 + 1]; \
        if (!diag) { \
            const float4* rq_ = (const float4*)(xb + (size_t)l_ * DDIM + c0B); \
            pb0 = rq_[cq * 2]; pb1 = rq_[cq * 2 + 1]; \
        } \
    } while (0)

#define CONVREGS(base_) do { \
        const uint32_t yaH_ = (base_); \
        const uint32_t yaL_ = (base_) + ABYTES; \
        uint32_t h0, h1, h2, h3, q0, q1, q2, q3; \
        split4(pa0, pw, h0, h1, q0, q1); \
        split4(pa1, pw, h2, h3, q2, q3); \
        STS128(yaH_ + cvoff, h0, h1, h2, h3); \
        STS128(yaL_ + cvoff, q0, q1, q2, q3); \
        if (!diag) { \
            const uint32_t ybH_ = (base_) + 2 * ABYTES; \
            const uint32_t ybL_ = (base_) + 3 * ABYTES; \
            split4(pb0, pw, h0, h1, q0, q1); \
            split4(pb1, pw, h2, h3, q2, q3); \
            STS128(ybH_ + cvoff, h0, h1, h2, h3); \
            STS128(ybL_ + cvoff, q0, q1, q2, q3); \
        } \
    } while (0)

#define MMASTEP(kk_, yaH_, yaL_, ybH_, ybL_) do { \
        const uint32_t krow_ = (uint32_t)((kk_) * 16) * SPB; \
        const uint32_t aBH_ = (yaH_) + offA + (uint32_t)(wy * 64); \
        const uint32_t aBL_ = (yaL_) + offA + (uint32_t)(wy * 64); \
        const uint32_t bBH_ = (ybH_) + offB + (uint32_t)(wx * 64); \
        const uint32_t bBL_ = (ybL_) + offB + (uint32_t)(wx * 64); \
        uint32_t ah[2][4], bh[2][4], xx[2][4]; \
        _Pragma("unroll") \
        for (int m = 0; m < 2; m++) ldsm4t(ah[m], aBH_ + krow_ + m * 32); \
        _Pragma("unroll") \
        for (int j = 0; j < 2; j++) ldsm4t(bh[j], bBH_ + krow_ + j * 32); \
        _Pragma("unroll") \
        for (int m = 0; m < 2; m++) \
            _Pragma("unroll") \
            for (int j = 0; j < 2; j++) { \
                mma16816(acc[m][j * 2 + 0], ah[m], bh[j][0], bh[j][1]); \
                mma16816(acc[m][j * 2 + 1], ah[m], bh[j][2], bh[j][3]); \
            } \
        _Pragma("unroll") \
        for (int j = 0; j < 2; j++) ldsm4t(xx[j], bBL_ + krow_ + j * 32); \
        _Pragma("unroll") \
        for (int m = 0; m < 2; m++) \
            _Pragma("unroll") \
            for (int j = 0; j < 2; j++) { \
                mma16816(acc[m][j * 2 + 0], ah[m], xx[j][0], xx[j][1]); \
                mma16816(acc[m][j * 2 + 1], ah[m], xx[j][2], xx[j][3]); \
            } \
        _Pragma("unroll") \
        for (int m = 0; m < 2; m++) ldsm4t(xx[m], aBL_ + krow_ + m * 32); \
        _Pragma("unroll") \
        for (int m = 0; m < 2; m++) \
            _Pragma("unroll") \
            for (int j = 0; j < 2; j++) { \
                mma16816(acc[m][j * 2 + 0], xx[m], bh[j][0], bh[j][1]); \
                mma16816(acc[m][j * 2 + 1], xx[m], bh[j][2], bh[j][3]); \
            } \
    } while (0)

    // -------- prologue: convert chunks c_start, c_start+1; LDG c_start+2 ----
    LOADREGS(c_start);
    CONVREGS(SLOTADDR(c_start));
    if (c_start + 1 < c_end) {
        LOADREGS(c_start + 1);
        CONVREGS(SLOTADDR(c_start + 1));
    }
    if (c_start + 2 < c_end) LOADREGS(c_start + 2);
    __syncthreads();

    for (int c = c_start; c < c_end; c++) {
        const uint32_t bM = SLOTADDR(c);
        const uint32_t yaH = bM;
        const uint32_t yaL = bM + ABYTES;
        const uint32_t ybH = diag ? yaH : bM + 2 * ABYTES;
        const uint32_t ybL = diag ? yaL : bM + 3 * ABYTES;

        MMASTEP(0, yaH, yaL, ybH, ybL);

        if (c + 2 < c_end) CONVREGS(SLOTADDR(c + 2));
        if (c + 3 < c_end) LOADREGS(c + 3);

        MMASTEP(1, yaH, yaL, ybH, ybL);

        if (((c - c_start) & 1) == 1) __syncthreads();
    }

    // ---- epilogue: write split-K partial tile ----
    float* dst = g_part + (((size_t)b * 3 + tile) * KSPLIT + s) * (128 * 128);
#pragma unroll
    for (int m = 0; m < 2; m++)
#pragma unroll
        for (int j = 0; j < 2; j++)
#pragma unroll
            for (int n = 0; n < 2; n++) {
                const int d = wy * 32 + m * 16 + (lane >> 2);
                const int e = wx * 32 + j * 16 + n * 8 + (lane & 3) * 2;
                float* cc = acc[m][j * 2 + n];
                *(float2*)(dst + d * 128 + e)       = make_float2(cc[0], cc[1]);
                *(float2*)(dst + (d + 8) * 128 + e) = make_float2(cc[2], cc[3]);
            }

#undef LOADREGS
#undef CONVREGS
#undef MMASTEP
#undef SLOTADDR
}

// ---------------------------------------------------------------------------
// Split-K reduce + symmetric mirror. idx over [B][3 tiles][128*128].
// ---------------------------------------------------------------------------
__global__ __launch_bounds__(256) void reduce_kernel(float* __restrict__ out)
{
    const int idx = blockIdx.x * 256 + threadIdx.x;
    const int b   = idx / (3 * 16384);
    const int rem = idx % (3 * 16384);
    const int t   = rem >> 14;
    const int dl  = (rem >> 7) & 127;
    const int el  = rem & 127;

    const float* p = g_part + (((size_t)b * 3 + t) * KSPLIT) * 16384 + dl * 128 + el;
    float v = 0.f;
#pragma unroll
    for (int s = 0; s < KSPLIT; s++) v += p[s * 16384];

    float* ob = out + (size_t)b * DDIM * DDIM;
    if (t == 0) {
        ob[dl * DDIM + el] = v;
    } else if (t == 2) {
        ob[(128 + dl) * DDIM + (128 + el)] = v;
    } else {
        ob[dl * DDIM + (128 + el)] = v;
        ob[(128 + el) * DDIM + dl] = v;     // mirror
    }
}

// ---------------------------------------------------------------------------
extern "C" void kernel_launch(void* const* d_in, const int* in_sizes, int n_in,
                              void* d_out, int out_size)
{
    const float* x = (const float*)d_in[0];
    float* out = (float*)d_out;

    cudaFuncSetAttribute(tensor_gemm, cudaFuncAttributeMaxDynamicSharedMemorySize, SM_TOT);

    norms_kernel<<<dim3(64, BATCH), 256>>>(x);
    sum_kernel<<<BATCH, 32>>>();
    tensor_gemm<<<dim3(3 * KSPLIT, BATCH), 512, SM_TOT>>>(x);
    reduce_kernel<<<BATCH * 3 * 16384 / 256, 256>>>(out);
}